// round 14
// baseline (speedup 1.0000x reference)
#include <cuda_runtime.h>
#include <math.h>
#include <stdint.h>

#define D_IN   768
#define TWO_D  1536
#define Q_N    128
#define S_N    512
#define C_N    64
#define JCHUNKS 16
#define JPER   (TWO_D / JCHUNKS)    /* 96 */
#define KSPLIT 384
#define NCB    (JCHUNKS * 4)        /* 64 chunk-blocks */

typedef unsigned long long ull;

// Scratch (device globals: allocation-free per harness rules)
__device__ float    v14_hq0[Q_N * TWO_D];
__device__ float    v14_hq1[Q_N * TWO_D];
__device__ float    v14_hs0[S_N * TWO_D];
__device__ float    v14_hs1[S_N * TWO_D];
__device__ double   v14_part2[NCB * Q_N * C_N];     // class-binned partials (4 MB)
__device__ double   v14_loss[Q_N];
__device__ unsigned v14_ticket = 0;

// fp32 -> tf32 RNA rounding (matches cuBLAS TF32 input quantization = reference)
__device__ __forceinline__ float v14_tf32(float x) {
    unsigned u;
    asm("cvt.rna.tf32.f32 %0, %1;" : "=r"(u) : "f"(x));
    return __uint_as_float(u);
}

// m16n8k8 tf32 mma (base ISA, sm_80+)
__device__ __forceinline__ void v14_mma(float d[4], const unsigned a[4], const unsigned b[2]) {
    asm volatile(
        "mma.sync.aligned.m16n8k8.row.col.f32.tf32.tf32.f32 "
        "{%0,%1,%2,%3}, {%4,%5,%6,%7}, {%8,%9}, {%0,%1,%2,%3};"
        : "+f"(d[0]), "+f"(d[1]), "+f"(d[2]), "+f"(d[3])
        : "r"(a[0]), "r"(a[1]), "r"(a[2]), "r"(a[3]), "r"(b[0]), "r"(b[1]));
}

#define V14_ADD2(d, a, b) \
    asm("add.rn.f32x2 %0, %1, %2;" : "=l"(d) : "l"(a), "l"(b))
#define V14_FMA2(acc, t, w) \
    asm("fma.rn.f32x2 %0, %1, %2, %0;" : "+l"(acc) : "l"(t), "l"(w))

// packed relu on the ALU pipe (IMAX): valid for all non-NaN floats
__device__ __forceinline__ ull v14_relu2(ull t) {
    unsigned lo, hi;
    asm("mov.b64 {%0,%1}, %2;" : "=r"(lo), "=r"(hi) : "l"(t));
    int l2 = max((int)lo, 0);
    int h2 = max((int)hi, 0);
    ull r;
    asm("mov.b64 %0, {%1,%2};" : "=l"(r) : "r"((unsigned)l2), "r"((unsigned)h2));
    return r;
}

// ---------------------------------------------------------------------------
// TF32 tensor-core GEMM, split-K x2 (VERBATIM best-measured R8/R11/R12 config).
// CTA 64m x 128n x K384; 12 double-buffered k-tiles of 32, one barrier/iter.
// 8 warps (2M x 4N), warp tile 32x32. grid = (12, 10, 2), occupancy 2.
// ---------------------------------------------------------------------------
#define V14_ST     40
#define V14_ASZ    (2 * 64 * V14_ST)
#define V14_BSZ    (2 * 128 * V14_ST)
#define V14_SMEM   ((V14_ASZ + V14_BSZ) * 4)

__global__ void __launch_bounds__(256, 2)
v14_gemm(const float* __restrict__ query,
         const float* __restrict__ support,
         const float* __restrict__ W1,
         const float* __restrict__ b1)
{
    extern __shared__ __align__(16) float smem[];
    float* As = smem;
    float* Bs = smem + V14_ASZ;

    const int tid  = threadIdx.x;
    const int lane = tid & 31;
    const int wid  = tid >> 5;
    const int warpM = wid & 1;
    const int warpN = wid >> 1;
    const int g = lane >> 2;
    const int t = lane & 3;

    const int  z    = blockIdx.z;
    const int  kOff = z * KSPLIT;
    const bool isQ  = (blockIdx.y < 2);
    const float* Arow = isQ ? (query + (size_t)blockIdx.y * 64 * D_IN)
                            : (support + (size_t)(blockIdx.y - 2) * 64 * D_IN);
    const int   wOff  = (isQ ? 0 : D_IN) + kOff;
    const int   jBase = blockIdx.x * 128;
    float* Hq = z ? v14_hq1 : v14_hq0;
    float* Hs = z ? v14_hs1 : v14_hs0;
    float* Crow = isQ ? (Hq + (size_t)blockIdx.y * 64 * TWO_D)
                      : (Hs + (size_t)(blockIdx.y - 2) * 64 * TWO_D);

    const int a_row = tid >> 2, a_ks = tid & 3;
    const int b_row0 = tid >> 2, b_ks0 = tid & 3;
    const int b_row1 = (tid + 256) >> 2, b_ks1 = tid & 3;
    const float* aSeg  = Arow + (size_t)a_row * D_IN + kOff + a_ks * 8;
    const float* bSeg0 = W1 + (size_t)(jBase + b_row0) * TWO_D + wOff + b_ks0 * 8;
    const float* bSeg1 = W1 + (size_t)(jBase + b_row1) * TWO_D + wOff + b_ks1 * 8;

    float4 pa0, pa1, pb00, pb01, pb10, pb11;
    #define V14_PREFETCH(kb) do {                                   \
        pa0  = *(const float4*)(aSeg  + (kb));                      \
        pa1  = *(const float4*)(aSeg  + (kb) + 4);                  \
        pb00 = *(const float4*)(bSeg0 + (kb));                      \
        pb01 = *(const float4*)(bSeg0 + (kb) + 4);                  \
        pb10 = *(const float4*)(bSeg1 + (kb));                      \
        pb11 = *(const float4*)(bSeg1 + (kb) + 4);                  \
    } while (0)

    #define V14_STAGE(buf) do {                                                     \
        float* ap = As + ((buf) * 64 + a_row) * V14_ST + a_ks * 8;                  \
        float2 p;                                                                   \
        p.x = v14_tf32(pa0.x); p.y = v14_tf32(pa1.x); *(float2*)(ap + 0) = p;       \
        p.x = v14_tf32(pa0.y); p.y = v14_tf32(pa1.y); *(float2*)(ap + 2) = p;       \
        p.x = v14_tf32(pa0.z); p.y = v14_tf32(pa1.z); *(float2*)(ap + 4) = p;       \
        p.x = v14_tf32(pa0.w); p.y = v14_tf32(pa1.w); *(float2*)(ap + 6) = p;       \
        float* bp = Bs + ((buf) * 128 + b_row0) * V14_ST + b_ks0 * 8;               \
        p.x = v14_tf32(pb00.x); p.y = v14_tf32(pb01.x); *(float2*)(bp + 0) = p;     \
        p.x = v14_tf32(pb00.y); p.y = v14_tf32(pb01.y); *(float2*)(bp + 2) = p;     \
        p.x = v14_tf32(pb00.z); p.y = v14_tf32(pb01.z); *(float2*)(bp + 4) = p;     \
        p.x = v14_tf32(pb00.w); p.y = v14_tf32(pb01.w); *(float2*)(bp + 6) = p;     \
        bp = Bs + ((buf) * 128 + b_row1) * V14_ST + b_ks1 * 8;                      \
        p.x = v14_tf32(pb10.x); p.y = v14_tf32(pb11.x); *(float2*)(bp + 0) = p;     \
        p.x = v14_tf32(pb10.y); p.y = v14_tf32(pb11.y); *(float2*)(bp + 2) = p;     \
        p.x = v14_tf32(pb10.z); p.y = v14_tf32(pb11.z); *(float2*)(bp + 4) = p;     \
        p.x = v14_tf32(pb10.w); p.y = v14_tf32(pb11.w); *(float2*)(bp + 6) = p;     \
    } while (0)

    float d[2][4][4] = {};

    V14_PREFETCH(0);
    V14_STAGE(0);
    V14_PREFETCH(32);

    for (int kt = 0; kt < 12; kt++) {
        const int buf = kt & 1;
        __syncthreads();
        if (kt < 11) {
            V14_STAGE(buf ^ 1);
            if (kt < 10) V14_PREFETCH((kt + 2) * 32);
        }

        const float* Ab = As + buf * 64 * V14_ST;
        const float* Bb = Bs + buf * 128 * V14_ST;
        #pragma unroll
        for (int s = 0; s < 4; s++) {
            unsigned afr[2][4];
            #pragma unroll
            for (int mf = 0; mf < 2; mf++) {
                const int r0 = warpM * 32 + mf * 16 + g;
                float2 p0 = *(const float2*)(Ab + r0 * V14_ST + s * 8 + t * 2);
                float2 p1 = *(const float2*)(Ab + (r0 + 8) * V14_ST + s * 8 + t * 2);
                afr[mf][0] = __float_as_uint(p0.x);
                afr[mf][1] = __float_as_uint(p1.x);
                afr[mf][2] = __float_as_uint(p0.y);
                afr[mf][3] = __float_as_uint(p1.y);
            }
            #pragma unroll
            for (int nf = 0; nf < 4; nf++) {
                const int n = warpN * 32 + nf * 8 + g;
                float2 q = *(const float2*)(Bb + n * V14_ST + s * 8 + t * 2);
                unsigned bfr[2] = { __float_as_uint(q.x), __float_as_uint(q.y) };
                v14_mma(d[0][nf], afr[0], bfr);
                v14_mma(d[1][nf], afr[1], bfr);
            }
        }
    }

    const bool addBias = isQ && (z == 0);
    #pragma unroll
    for (int mf = 0; mf < 2; mf++) {
        const int r0 = warpM * 32 + mf * 16 + g;
        #pragma unroll
        for (int nf = 0; nf < 4; nf++) {
            const int c0 = jBase + warpN * 32 + nf * 8 + t * 2;
            float2 bias = make_float2(0.f, 0.f);
            if (addBias) bias = *(const float2*)(b1 + c0);
            float2 v0 = make_float2(d[mf][nf][0] + bias.x, d[mf][nf][1] + bias.y);
            float2 v1 = make_float2(d[mf][nf][2] + bias.x, d[mf][nf][3] + bias.y);
            *(float2*)(Crow + (size_t)r0 * TWO_D + c0)       = v0;
            *(float2*)(Crow + (size_t)(r0 + 8) * TWO_D + c0) = v1;
        }
    }
}

// ---------------------------------------------------------------------------
// Scores + class binning (R12 structure, JPER=96 -> grid 256 blocks for
// 2 blocks/SM = 4 warps/SMSP latency hiding).
// grid = (4 s-tiles, 4 q-stripes, 16 j-chunks), 256 threads.
// ---------------------------------------------------------------------------
#define V14S_DYN   33824   /* bytes: scr 33024 + lab 512 + seg 260 + pad */

__global__ void __launch_bounds__(256, 2)
v14_scores(const float* __restrict__ W2, const int* __restrict__ labels)
{
    extern __shared__ __align__(16) char dyn[];
    float2* Aq2 = (float2*)(dyn);                 // [2][8][34]
    float2* Bs2 = (float2*)(dyn + 4352);          // [2][8][130]
    float2* ws2 = (float2*)(dyn + 20992);         // [2][8]
    double* scr  = (double*)(dyn);                // [32][129] (phase 2 overlay)
    int*    lab2 = (int*)(dyn + 33024);           // [128]
    int*    seg  = (int*)(dyn + 33536);           // [65]

    const int tid    = threadIdx.x;
    const int sBase  = blockIdx.x * 128;
    const int qBase  = blockIdx.y * 32;
    const int jcBase = blockIdx.z * JPER;
    const int ty = tid >> 4;      // q rows ty*2, ty*2+1
    const int tx = tid & 15;      // s cols tx + l*16, l=0..7

    const int aq_q  = tid >> 3;
    const int aq_jp = tid & 7;
    const size_t hqOff = (size_t)(qBase + aq_q) * TWO_D + jcBase + aq_jp * 2;
    const int bs_s  = tid >> 1;
    const int bs_h  = (tid & 1) * 8;
    const int bs_jp = bs_h >> 1;
    const size_t hsOff = (size_t)(sBase + bs_s) * TWO_D + jcBase + bs_h;

    float2 pa0, pa1, pw;
    float4 pb00, pb01, pb10, pb11;

    #define V14S_PRE(jt) do {                                          \
        pa0  = *(const float2*)(v14_hq0 + hqOff + (jt));               \
        pa1  = *(const float2*)(v14_hq1 + hqOff + (jt));               \
        pb00 = *(const float4*)(v14_hs0 + hsOff + (jt));               \
        pb01 = *(const float4*)(v14_hs0 + hsOff + (jt) + 4);           \
        pb10 = *(const float4*)(v14_hs1 + hsOff + (jt));               \
        pb11 = *(const float4*)(v14_hs1 + hsOff + (jt) + 4);           \
        if (tid < 8) pw = *(const float2*)(W2 + jcBase + (jt) + tid * 2); \
    } while (0)

    #define V14S_STAGE(buf) do {                                                            \
        Aq2[(buf)*272 + aq_jp*34 + aq_q] = make_float2(pa0.x + pa1.x, pa0.y + pa1.y);       \
        Bs2[(buf)*1040 + (bs_jp+0)*130 + bs_s] = make_float2(pb00.x + pb10.x, pb00.y + pb10.y); \
        Bs2[(buf)*1040 + (bs_jp+1)*130 + bs_s] = make_float2(pb00.z + pb10.z, pb00.w + pb10.w); \
        Bs2[(buf)*1040 + (bs_jp+2)*130 + bs_s] = make_float2(pb01.x + pb11.x, pb01.y + pb11.y); \
        Bs2[(buf)*1040 + (bs_jp+3)*130 + bs_s] = make_float2(pb01.z + pb11.z, pb01.w + pb11.w); \
        if (tid < 8) ws2[(buf)*8 + tid] = pw;                                               \
    } while (0)

    ull acc2[2][8] = {};

    V14S_PRE(0);
    V14S_STAGE(0);
    V14S_PRE(16);

    for (int it = 0; it < 6; it++) {
        const int buf = it & 1;
        __syncthreads();
        if (it < 5) {
            V14S_STAGE(buf ^ 1);
            if (it < 4) V14S_PRE((it + 2) * 16);
        }

        #pragma unroll
        for (int jp = 0; jp < 8; jp++) {
            const ull w2v = *(const ull*)&ws2[buf*8 + jp];
            // one LDS128: rows ty*2 and ty*2+1 are adjacent 16B-aligned float2s
            float4 apair = *(const float4*)&Aq2[buf*272 + jp*34 + ty*2];
            ull a0, a1;
            asm("mov.b64 %0, {%1,%2};" : "=l"(a0)
                : "r"(__float_as_uint(apair.x)), "r"(__float_as_uint(apair.y)));
            asm("mov.b64 %0, {%1,%2};" : "=l"(a1)
                : "r"(__float_as_uint(apair.z)), "r"(__float_as_uint(apair.w)));
            #pragma unroll
            for (int l = 0; l < 8; l++) {
                const ull bv = *(const ull*)&Bs2[buf*1040 + jp*130 + tx + l*16];
                ull t0; V14_ADD2(t0, a0, bv);
                t0 = v14_relu2(t0);
                V14_FMA2(acc2[0][l], t0, w2v);
                ull t1; V14_ADD2(t1, a1, bv);
                t1 = v14_relu2(t1);
                V14_FMA2(acc2[1][l], t1, w2v);
            }
        }
    }

    // ---- phase 2: overlay smem, write chunk scores, bin by class ----
    __syncthreads();

    #pragma unroll
    for (int i = 0; i < 2; i++)
        #pragma unroll
        for (int l = 0; l < 8; l++) {
            unsigned lo, hi;
            asm("mov.b64 {%0,%1}, %2;" : "=r"(lo), "=r"(hi) : "l"(acc2[i][l]));
            scr[(ty*2 + i) * 129 + tx + l*16] =
                (double)(__uint_as_float(lo) + __uint_as_float(hi));
        }
    if (tid < 128) lab2[tid] = labels[sBase + tid];
    __syncthreads();

    if (tid <= 64) {
        const int c = tid;
        int lo = 0, hi = 128;
        while (lo < hi) { int m = (lo + hi) >> 1; if (lab2[m] < c) lo = m + 1; else hi = m; }
        seg[tid] = lo;
    }
    __syncthreads();

    const int cb = blockIdx.z * 4 + blockIdx.x;
    double* outp = v14_part2 + ((size_t)cb * Q_N + qBase) * C_N;
    #pragma unroll
    for (int k = 0; k < 8; k++) {
        const int p  = tid + k * 256;
        const int qq = p >> 6;
        const int cc = p & 63;
        double ssum = 0.0;
        const int s0 = seg[cc], s1 = seg[cc + 1];
        for (int s = s0; s < s1; s++) ssum += scr[qq * 129 + s];
        outp[p] = ssum;
    }
}

// ---------------------------------------------------------------------------
// Light aggregate (R12 structure, NCB=64): per-query block sums class-binned
// partials in fixed order, counts via binary search, softmax/argmax/loss,
// ticket-merged final. grid = 128 blocks, 128 threads.
// ---------------------------------------------------------------------------
__global__ void v14_agg(const int* __restrict__ labels,
                        const int* __restrict__ targets,
                        const float* __restrict__ b2,
                        float* __restrict__ out, int out_size)
{
    __shared__ int    lab[S_N];
    __shared__ double aggv[C_N];
    __shared__ double redv[C_N];
    __shared__ int    redi[C_N];
    __shared__ double rede[C_N];
    __shared__ int    isLast;
    __shared__ double lred[Q_N];

    const int q   = blockIdx.x;
    const int tid = threadIdx.x;

    for (int i = tid; i < S_N; i += 128) lab[i] = labels[i];
    __syncthreads();

    if (tid < C_N) {
        const double* P = v14_part2 + (size_t)q * C_N + tid;
        double s0 = 0.0, s1 = 0.0, s2 = 0.0, s3 = 0.0;
        #pragma unroll
        for (int cb = 0; cb < NCB; cb += 4) {
            s0 += P[(size_t)(cb + 0) * (Q_N * C_N)];
            s1 += P[(size_t)(cb + 1) * (Q_N * C_N)];
            s2 += P[(size_t)(cb + 2) * (Q_N * C_N)];
            s3 += P[(size_t)(cb + 3) * (Q_N * C_N)];
        }
        const double tot = (s0 + s1) + (s2 + s3);

        const int c = tid;
        int lo = 0, hi = S_N;
        while (lo < hi) { int m = (lo + hi) >> 1; if (lab[m] < c) lo = m + 1; else hi = m; }
        int lo2 = lo, hi2 = S_N;
        while (lo2 < hi2) { int m = (lo2 + hi2) >> 1; if (lab[m] < c + 1) lo2 = m + 1; else hi2 = m; }
        const int cnt = lo2 - lo;

        aggv[tid] = tot / (double)(cnt > 1 ? cnt : 1) + (double)b2[0];
        redv[tid] = aggv[tid];
        redi[tid] = tid;
    }
    __syncthreads();

    #pragma unroll
    for (int off = C_N / 2; off > 0; off >>= 1) {
        if (tid < off) {
            if (redv[tid + off] > redv[tid] ||
                (redv[tid + off] == redv[tid] && redi[tid + off] < redi[tid])) {
                redv[tid] = redv[tid + off];
                redi[tid] = redi[tid + off];
            }
        }
        __syncthreads();
    }
    const double mx = redv[0];
    const int    am = redi[0];

    if (tid < C_N) rede[tid] = exp(aggv[tid] - mx);
    __syncthreads();
    #pragma unroll
    for (int off = C_N / 2; off > 0; off >>= 1) {
        if (tid < off) rede[tid] += rede[tid + off];
        __syncthreads();
    }

    if (tid == 0) {
        const int tgt = targets[q];
        const double logp = aggv[tgt] - mx - log(rede[0]);
        v14_loss[q] = -logp;
        if (1 + q < out_size) out[1 + q] = (am == tgt) ? 1.0f : 0.0f;
        __threadfence();
        unsigned tk = atomicAdd(&v14_ticket, 1u);
        isLast = (tk == (unsigned)(Q_N - 1));
    }
    __syncthreads();

    if (isLast) {
        __threadfence();
        lred[tid] = v14_loss[tid];
        __syncthreads();
        #pragma unroll
        for (int off = Q_N / 2; off > 0; off >>= 1) {
            if (tid < off) lred[tid] += lred[tid + off];
            __syncthreads();
        }
        if (tid == 0) {
            if (out_size > 0) out[0] = (float)(lred[0] / (double)Q_N);
            v14_ticket = 0;
        }
    }
}

// ---------------------------------------------------------------------------
extern "C" void kernel_launch(void* const* d_in, const int* in_sizes, int n_in,
                              void* d_out, int out_size)
{
    const float* query   = (const float*)d_in[0];
    const float* support = (const float*)d_in[1];
    const float* W1      = (const float*)d_in[2];
    const float* b1      = (const float*)d_in[3];
    const float* W2      = (const float*)d_in[4];
    const float* b2      = (const float*)d_in[5];
    const int*   labels  = (const int*)  d_in[6];
    const int*   targets = (const int*)  d_in[7];
    (void)in_sizes; (void)n_in;

    float* out = (float*)d_out;

    cudaFuncSetAttribute(v14_gemm, cudaFuncAttributeMaxDynamicSharedMemorySize, V14_SMEM);

    v14_gemm  <<<dim3(12, 10, 2), 256, V14_SMEM>>>(query, support, W1, b1);
    v14_scores<<<dim3(4, 4, JCHUNKS), 256, V14S_DYN>>>(W2, labels);
    v14_agg   <<<Q_N, 128>>>(labels, targets, b2, out, out_size);
}

// round 15
// speedup vs baseline: 1.1594x; 1.1594x over previous
#include <cuda_runtime.h>
#include <math.h>
#include <stdint.h>

#define D_IN   768
#define TWO_D  1536
#define Q_N    128
#define S_N    512
#define C_N    64
#define JCHUNKS 8
#define JPER   (TWO_D / JCHUNKS)    /* 192 */
#define KSPLIT 384
#define NCB    32                   /* chunk-blocks = JCHUNKS * 4 s-tiles */

typedef unsigned long long ull;

// Scratch (device globals: allocation-free per harness rules)
__device__ float    v15_hq0[Q_N * TWO_D];
__device__ float    v15_hq1[Q_N * TWO_D];
__device__ float    v15_hs0[S_N * TWO_D];
__device__ float    v15_hs1[S_N * TWO_D];
__device__ double   v15_part2[NCB * Q_N * C_N];     // class-binned partials (2 MB)
__device__ double   v15_loss[Q_N];
__device__ unsigned v15_ticket = 0;

// fp32 -> tf32 RNA rounding (matches cuBLAS TF32 input quantization = reference)
__device__ __forceinline__ float v15_tf32(float x) {
    unsigned u;
    asm("cvt.rna.tf32.f32 %0, %1;" : "=r"(u) : "f"(x));
    return __uint_as_float(u);
}

// m16n8k8 tf32 mma (base ISA, sm_80+)
__device__ __forceinline__ void v15_mma(float d[4], const unsigned a[4], const unsigned b[2]) {
    asm volatile(
        "mma.sync.aligned.m16n8k8.row.col.f32.tf32.tf32.f32 "
        "{%0,%1,%2,%3}, {%4,%5,%6,%7}, {%8,%9}, {%0,%1,%2,%3};"
        : "+f"(d[0]), "+f"(d[1]), "+f"(d[2]), "+f"(d[3])
        : "r"(a[0]), "r"(a[1]), "r"(a[2]), "r"(a[3]), "r"(b[0]), "r"(b[1]));
}

#define V15_ADD2(d, a, b) \
    asm("add.rn.f32x2 %0, %1, %2;" : "=l"(d) : "l"(a), "l"(b))
#define V15_FMA2(acc, t, w) \
    asm("fma.rn.f32x2 %0, %1, %2, %0;" : "+l"(acc) : "l"(t), "l"(w))

// packed relu on the ALU pipe (IMAX): valid for all non-NaN floats
__device__ __forceinline__ ull v15_relu2(ull t) {
    unsigned lo, hi;
    asm("mov.b64 {%0,%1}, %2;" : "=r"(lo), "=r"(hi) : "l"(t));
    int l2 = max((int)lo, 0);
    int h2 = max((int)hi, 0);
    ull r;
    asm("mov.b64 %0, {%1,%2};" : "=l"(r) : "r"((unsigned)l2), "r"((unsigned)h2));
    return r;
}

// ---------------------------------------------------------------------------
// TF32 tensor-core GEMM, split-K x2 (VERBATIM best-measured R8/R11/R12 config).
// CTA 64m x 128n x K384; 12 double-buffered k-tiles of 32, one barrier/iter.
// 8 warps (2M x 4N), warp tile 32x32. grid = (12, 10, 2), occupancy 2.
// ---------------------------------------------------------------------------
#define V15_ST     40
#define V15_ASZ    (2 * 64 * V15_ST)
#define V15_BSZ    (2 * 128 * V15_ST)
#define V15_SMEM   ((V15_ASZ + V15_BSZ) * 4)

__global__ void __launch_bounds__(256, 2)
v15_gemm(const float* __restrict__ query,
         const float* __restrict__ support,
         const float* __restrict__ W1,
         const float* __restrict__ b1)
{
    extern __shared__ __align__(16) float smem[];
    float* As = smem;
    float* Bs = smem + V15_ASZ;

    const int tid  = threadIdx.x;
    const int lane = tid & 31;
    const int wid  = tid >> 5;
    const int warpM = wid & 1;
    const int warpN = wid >> 1;
    const int g = lane >> 2;
    const int t = lane & 3;

    const int  z    = blockIdx.z;
    const int  kOff = z * KSPLIT;
    const bool isQ  = (blockIdx.y < 2);
    const float* Arow = isQ ? (query + (size_t)blockIdx.y * 64 * D_IN)
                            : (support + (size_t)(blockIdx.y - 2) * 64 * D_IN);
    const int   wOff  = (isQ ? 0 : D_IN) + kOff;
    const int   jBase = blockIdx.x * 128;
    float* Hq = z ? v15_hq1 : v15_hq0;
    float* Hs = z ? v15_hs1 : v15_hs0;
    float* Crow = isQ ? (Hq + (size_t)blockIdx.y * 64 * TWO_D)
                      : (Hs + (size_t)(blockIdx.y - 2) * 64 * TWO_D);

    const int a_row = tid >> 2, a_ks = tid & 3;
    const int b_row0 = tid >> 2, b_ks0 = tid & 3;
    const int b_row1 = (tid + 256) >> 2, b_ks1 = tid & 3;
    const float* aSeg  = Arow + (size_t)a_row * D_IN + kOff + a_ks * 8;
    const float* bSeg0 = W1 + (size_t)(jBase + b_row0) * TWO_D + wOff + b_ks0 * 8;
    const float* bSeg1 = W1 + (size_t)(jBase + b_row1) * TWO_D + wOff + b_ks1 * 8;

    float4 pa0, pa1, pb00, pb01, pb10, pb11;
    #define V15_PREFETCH(kb) do {                                   \
        pa0  = *(const float4*)(aSeg  + (kb));                      \
        pa1  = *(const float4*)(aSeg  + (kb) + 4);                  \
        pb00 = *(const float4*)(bSeg0 + (kb));                      \
        pb01 = *(const float4*)(bSeg0 + (kb) + 4);                  \
        pb10 = *(const float4*)(bSeg1 + (kb));                      \
        pb11 = *(const float4*)(bSeg1 + (kb) + 4);                  \
    } while (0)

    #define V15_STAGE(buf) do {                                                     \
        float* ap = As + ((buf) * 64 + a_row) * V15_ST + a_ks * 8;                  \
        float2 p;                                                                   \
        p.x = v15_tf32(pa0.x); p.y = v15_tf32(pa1.x); *(float2*)(ap + 0) = p;       \
        p.x = v15_tf32(pa0.y); p.y = v15_tf32(pa1.y); *(float2*)(ap + 2) = p;       \
        p.x = v15_tf32(pa0.z); p.y = v15_tf32(pa1.z); *(float2*)(ap + 4) = p;       \
        p.x = v15_tf32(pa0.w); p.y = v15_tf32(pa1.w); *(float2*)(ap + 6) = p;       \
        float* bp = Bs + ((buf) * 128 + b_row0) * V15_ST + b_ks0 * 8;               \
        p.x = v15_tf32(pb00.x); p.y = v15_tf32(pb01.x); *(float2*)(bp + 0) = p;     \
        p.x = v15_tf32(pb00.y); p.y = v15_tf32(pb01.y); *(float2*)(bp + 2) = p;     \
        p.x = v15_tf32(pb00.z); p.y = v15_tf32(pb01.z); *(float2*)(bp + 4) = p;     \
        p.x = v15_tf32(pb00.w); p.y = v15_tf32(pb01.w); *(float2*)(bp + 6) = p;     \
        bp = Bs + ((buf) * 128 + b_row1) * V15_ST + b_ks1 * 8;                      \
        p.x = v15_tf32(pb10.x); p.y = v15_tf32(pb11.x); *(float2*)(bp + 0) = p;     \
        p.x = v15_tf32(pb10.y); p.y = v15_tf32(pb11.y); *(float2*)(bp + 2) = p;     \
        p.x = v15_tf32(pb10.z); p.y = v15_tf32(pb11.z); *(float2*)(bp + 4) = p;     \
        p.x = v15_tf32(pb10.w); p.y = v15_tf32(pb11.w); *(float2*)(bp + 6) = p;     \
    } while (0)

    float d[2][4][4] = {};

    V15_PREFETCH(0);
    V15_STAGE(0);
    V15_PREFETCH(32);

    for (int kt = 0; kt < 12; kt++) {
        const int buf = kt & 1;
        __syncthreads();
        if (kt < 11) {
            V15_STAGE(buf ^ 1);
            if (kt < 10) V15_PREFETCH((kt + 2) * 32);
        }

        const float* Ab = As + buf * 64 * V15_ST;
        const float* Bb = Bs + buf * 128 * V15_ST;
        #pragma unroll
        for (int s = 0; s < 4; s++) {
            unsigned afr[2][4];
            #pragma unroll
            for (int mf = 0; mf < 2; mf++) {
                const int r0 = warpM * 32 + mf * 16 + g;
                float2 p0 = *(const float2*)(Ab + r0 * V15_ST + s * 8 + t * 2);
                float2 p1 = *(const float2*)(Ab + (r0 + 8) * V15_ST + s * 8 + t * 2);
                afr[mf][0] = __float_as_uint(p0.x);
                afr[mf][1] = __float_as_uint(p1.x);
                afr[mf][2] = __float_as_uint(p0.y);
                afr[mf][3] = __float_as_uint(p1.y);
            }
            #pragma unroll
            for (int nf = 0; nf < 4; nf++) {
                const int n = warpN * 32 + nf * 8 + g;
                float2 q = *(const float2*)(Bb + n * V15_ST + s * 8 + t * 2);
                unsigned bfr[2] = { __float_as_uint(q.x), __float_as_uint(q.y) };
                v15_mma(d[0][nf], afr[0], bfr);
                v15_mma(d[1][nf], afr[1], bfr);
            }
        }
    }

    const bool addBias = isQ && (z == 0);
    #pragma unroll
    for (int mf = 0; mf < 2; mf++) {
        const int r0 = warpM * 32 + mf * 16 + g;
        #pragma unroll
        for (int nf = 0; nf < 4; nf++) {
            const int c0 = jBase + warpN * 32 + nf * 8 + t * 2;
            float2 bias = make_float2(0.f, 0.f);
            if (addBias) bias = *(const float2*)(b1 + c0);
            float2 v0 = make_float2(d[mf][nf][0] + bias.x, d[mf][nf][1] + bias.y);
            float2 v1 = make_float2(d[mf][nf][2] + bias.x, d[mf][nf][3] + bias.y);
            *(float2*)(Crow + (size_t)r0 * TWO_D + c0)       = v0;
            *(float2*)(Crow + (size_t)(r0 + 8) * TWO_D + c0) = v1;
        }
    }
}

// ---------------------------------------------------------------------------
// Scores + class binning, 512 threads (R12 tile/interface; 2q x 4s per thread,
// 16 warps/block -> 4 warps/SMSP at 2 blocks/SM; same 128 epilogues as R12).
// grid = (4 s-tiles, 4 q-stripes, 8 j-chunks), 512 threads.
// Accumulation order per (q,s) identical to R12 -> bit-identical output.
// ---------------------------------------------------------------------------
#define V15S_DYN   33824   /* bytes: scr 33024 + lab 512 + seg 260 + pad */

__global__ void __launch_bounds__(512, 2)
v15_scores(const float* __restrict__ W2, const int* __restrict__ labels)
{
    extern __shared__ __align__(16) char dyn[];
    float2* Aq2 = (float2*)(dyn);                 // [2][8][34]
    float2* Bs2 = (float2*)(dyn + 4352);          // [2][8][130]
    float2* ws2 = (float2*)(dyn + 20992);         // [2][8]
    double* scr  = (double*)(dyn);                // [32][129] (phase 2 overlay)
    int*    lab2 = (int*)(dyn + 33024);           // [128]
    int*    seg  = (int*)(dyn + 33536);           // [65]

    const int tid    = threadIdx.x;
    const int sBase  = blockIdx.x * 128;
    const int qBase  = blockIdx.y * 32;
    const int jcBase = blockIdx.z * JPER;
    const int ty = tid >> 5;      // 0..15: q rows ty*2, ty*2+1
    const int tx = tid & 31;      // s cols tx + l*32, l=0..3

    // A staging: threads 0..255, one f32x2 each (32 q x 8 jp)
    const int aq_q  = (tid >> 3) & 31;
    const int aq_jp = tid & 7;
    const size_t hqOff = (size_t)(qBase + aq_q) * TWO_D + jcBase + aq_jp * 2;
    // B staging: all 512, one float4-pair each (128 s x 4 j-groups of 4)
    const int bs_s  = tid >> 2;          // 0..127
    const int bs_g  = tid & 3;           // j group: j = g*4..g*4+3 -> jp = g*2, g*2+1
    const size_t hsOff = (size_t)(sBase + bs_s) * TWO_D + jcBase + bs_g * 4;

    float2 pa0, pa1, pw;
    float4 pb0, pb1;

    #define V15S_PRE(jt) do {                                              \
        if (tid < 256) {                                                   \
            pa0 = *(const float2*)(v15_hq0 + hqOff + (jt));                \
            pa1 = *(const float2*)(v15_hq1 + hqOff + (jt));                \
        }                                                                  \
        pb0 = *(const float4*)(v15_hs0 + hsOff + (jt));                    \
        pb1 = *(const float4*)(v15_hs1 + hsOff + (jt));                    \
        if (tid < 8) pw = *(const float2*)(W2 + jcBase + (jt) + tid * 2);  \
    } while (0)

    #define V15S_STAGE(buf) do {                                                            \
        if (tid < 256)                                                                       \
            Aq2[(buf)*272 + aq_jp*34 + aq_q] = make_float2(pa0.x + pa1.x, pa0.y + pa1.y);   \
        Bs2[(buf)*1040 + (bs_g*2+0)*130 + bs_s] = make_float2(pb0.x + pb1.x, pb0.y + pb1.y);\
        Bs2[(buf)*1040 + (bs_g*2+1)*130 + bs_s] = make_float2(pb0.z + pb1.z, pb0.w + pb1.w);\
        if (tid < 8) ws2[(buf)*8 + tid] = pw;                                               \
    } while (0)

    ull acc2[2][4] = {};

    V15S_PRE(0);
    V15S_STAGE(0);
    V15S_PRE(16);

    for (int it = 0; it < 12; it++) {
        const int buf = it & 1;
        __syncthreads();
        if (it < 11) {
            V15S_STAGE(buf ^ 1);
            if (it < 10) V15S_PRE((it + 2) * 16);
        }

        #pragma unroll
        for (int jp = 0; jp < 8; jp++) {
            const ull w2v = *(const ull*)&ws2[buf*8 + jp];
            // one LDS128 (warp-uniform broadcast): q-pair rows ty*2, ty*2+1
            float4 apair = *(const float4*)&Aq2[buf*272 + jp*34 + ty*2];
            ull a0, a1;
            asm("mov.b64 %0, {%1,%2};" : "=l"(a0)
                : "r"(__float_as_uint(apair.x)), "r"(__float_as_uint(apair.y)));
            asm("mov.b64 %0, {%1,%2};" : "=l"(a1)
                : "r"(__float_as_uint(apair.z)), "r"(__float_as_uint(apair.w)));
            #pragma unroll
            for (int l = 0; l < 4; l++) {
                const ull bv = *(const ull*)&Bs2[buf*1040 + jp*130 + tx + l*32];
                ull t0; V15_ADD2(t0, a0, bv);
                t0 = v15_relu2(t0);
                V15_FMA2(acc2[0][l], t0, w2v);
                ull t1; V15_ADD2(t1, a1, bv);
                t1 = v15_relu2(t1);
                V15_FMA2(acc2[1][l], t1, w2v);
            }
        }
    }

    // ---- phase 2: overlay smem, write chunk scores, bin by class ----
    __syncthreads();

    #pragma unroll
    for (int i = 0; i < 2; i++)
        #pragma unroll
        for (int l = 0; l < 4; l++) {
            unsigned lo, hi;
            asm("mov.b64 {%0,%1}, %2;" : "=r"(lo), "=r"(hi) : "l"(acc2[i][l]));
            scr[(ty*2 + i) * 129 + tx + l*32] =
                (double)(__uint_as_float(lo) + __uint_as_float(hi));
        }
    if (tid < 128) lab2[tid] = labels[sBase + tid];
    __syncthreads();

    if (tid <= 64) {
        const int c = tid;
        int lo = 0, hi = 128;
        while (lo < hi) { int m = (lo + hi) >> 1; if (lab2[m] < c) lo = m + 1; else hi = m; }
        seg[tid] = lo;
    }
    __syncthreads();

    const int cb = blockIdx.z * 4 + blockIdx.x;
    double* outp = v15_part2 + ((size_t)cb * Q_N + qBase) * C_N;
    #pragma unroll
    for (int k = 0; k < 4; k++) {
        const int p  = tid + k * 512;
        const int qq = p >> 6;
        const int cc = p & 63;
        double ssum = 0.0;
        const int s0 = seg[cc], s1 = seg[cc + 1];
        for (int s = s0; s < s1; s++) ssum += scr[qq * 129 + s];
        outp[p] = ssum;
    }
}

// ---------------------------------------------------------------------------
// Light aggregate (VERBATIM R12): per-query block sums 32 class-binned
// partials in fixed order, counts via binary search, softmax/argmax/loss,
// ticket-merged final. grid = 128 blocks, 128 threads.
// ---------------------------------------------------------------------------
__global__ void v15_agg(const int* __restrict__ labels,
                        const int* __restrict__ targets,
                        const float* __restrict__ b2,
                        float* __restrict__ out, int out_size)
{
    __shared__ int    lab[S_N];
    __shared__ double aggv[C_N];
    __shared__ double redv[C_N];
    __shared__ int    redi[C_N];
    __shared__ double rede[C_N];
    __shared__ int    isLast;
    __shared__ double lred[Q_N];

    const int q   = blockIdx.x;
    const int tid = threadIdx.x;

    for (int i = tid; i < S_N; i += 128) lab[i] = labels[i];
    __syncthreads();

    if (tid < C_N) {
        const double* P = v15_part2 + (size_t)q * C_N + tid;
        double s0 = 0.0, s1 = 0.0, s2 = 0.0, s3 = 0.0;
        #pragma unroll
        for (int cb = 0; cb < NCB; cb += 4) {
            s0 += P[(size_t)(cb + 0) * (Q_N * C_N)];
            s1 += P[(size_t)(cb + 1) * (Q_N * C_N)];
            s2 += P[(size_t)(cb + 2) * (Q_N * C_N)];
            s3 += P[(size_t)(cb + 3) * (Q_N * C_N)];
        }
        const double tot = (s0 + s1) + (s2 + s3);

        const int c = tid;
        int lo = 0, hi = S_N;
        while (lo < hi) { int m = (lo + hi) >> 1; if (lab[m] < c) lo = m + 1; else hi = m; }
        int lo2 = lo, hi2 = S_N;
        while (lo2 < hi2) { int m = (lo2 + hi2) >> 1; if (lab[m] < c + 1) lo2 = m + 1; else hi2 = m; }
        const int cnt = lo2 - lo;

        aggv[tid] = tot / (double)(cnt > 1 ? cnt : 1) + (double)b2[0];
        redv[tid] = aggv[tid];
        redi[tid] = tid;
    }
    __syncthreads();

    #pragma unroll
    for (int off = C_N / 2; off > 0; off >>= 1) {
        if (tid < off) {
            if (redv[tid + off] > redv[tid] ||
                (redv[tid + off] == redv[tid] && redi[tid + off] < redi[tid])) {
                redv[tid] = redv[tid + off];
                redi[tid] = redi[tid + off];
            }
        }
        __syncthreads();
    }
    const double mx = redv[0];
    const int    am = redi[0];

    if (tid < C_N) rede[tid] = exp(aggv[tid] - mx);
    __syncthreads();
    #pragma unroll
    for (int off = C_N / 2; off > 0; off >>= 1) {
        if (tid < off) rede[tid] += rede[tid + off];
        __syncthreads();
    }

    if (tid == 0) {
        const int tgt = targets[q];
        const double logp = aggv[tgt] - mx - log(rede[0]);
        v15_loss[q] = -logp;
        if (1 + q < out_size) out[1 + q] = (am == tgt) ? 1.0f : 0.0f;
        __threadfence();
        unsigned tk = atomicAdd(&v15_ticket, 1u);
        isLast = (tk == (unsigned)(Q_N - 1));
    }
    __syncthreads();

    if (isLast) {
        __threadfence();
        lred[tid] = v15_loss[tid];
        __syncthreads();
        #pragma unroll
        for (int off = Q_N / 2; off > 0; off >>= 1) {
            if (tid < off) lred[tid] += lred[tid + off];
            __syncthreads();
        }
        if (tid == 0) {
            if (out_size > 0) out[0] = (float)(lred[0] / (double)Q_N);
            v15_ticket = 0;
        }
    }
}

// ---------------------------------------------------------------------------
extern "C" void kernel_launch(void* const* d_in, const int* in_sizes, int n_in,
                              void* d_out, int out_size)
{
    const float* query   = (const float*)d_in[0];
    const float* support = (const float*)d_in[1];
    const float* W1      = (const float*)d_in[2];
    const float* b1      = (const float*)d_in[3];
    const float* W2      = (const float*)d_in[4];
    const float* b2      = (const float*)d_in[5];
    const int*   labels  = (const int*)  d_in[6];
    const int*   targets = (const int*)  d_in[7];
    (void)in_sizes; (void)n_in;

    float* out = (float*)d_out;

    cudaFuncSetAttribute(v15_gemm, cudaFuncAttributeMaxDynamicSharedMemorySize, V15_SMEM);

    v15_gemm  <<<dim3(12, 10, 2), 256, V15_SMEM>>>(query, support, W1, b1);
    v15_scores<<<dim3(4, 4, JCHUNKS), 512, V15S_DYN>>>(W2, labels);
    v15_agg   <<<Q_N, 128>>>(labels, targets, b2, out, out_size);
}